// round 13
// baseline (speedup 1.0000x reference)
#include <cuda_runtime.h>
#include <cuda_bf16.h>
#include <cstdint>
#include <math.h>

#define BSZ   4096
#define NROWS 8192
#define DDIM  256
#define EPSF      1e-8f
#define COS_EPSF  1e-8f
#define INV_SQRT_TAU 1.4142135623730951f   // 1/sqrt(0.5)
#define LOG2E 1.4426950408889634f

#define TILE 128
#define PAIRD 32                           // BSZ / TILE: block distance of pos pairs
#define STAGE_BYTES (TILE * 128)           // 16 KB per operand per stage (BK=64 bf16)
#define SMEM_BYTES (4 * STAGE_BYTES)       // A0,B0,A1,B1 = 64 KB

// Scratch (device globals; no allocation allowed)
__device__ __nv_bfloat16 g_zn[NROWS * DDIM];   // normalized * 1/sqrt(tau)
__device__ float g_negsum[NROWS];
__device__ float g_spos[NROWS];

__device__ __forceinline__ uint32_t smem_u32(const void* p) {
    uint32_t a;
    asm("{ .reg .u64 t; cvta.to.shared.u64 t, %1; cvt.u32.u64 %0, t; }"
        : "=r"(a) : "l"(p));
    return a;
}
__device__ __forceinline__ void cp16(uint32_t dst, const void* src) {
    asm volatile("cp.async.cg.shared.global [%0], [%1], 16;"
                 :: "r"(dst), "l"(src) : "memory");
}
#define CP_COMMIT() asm volatile("cp.async.commit_group;" ::: "memory")
#define CP_WAIT0()  asm volatile("cp.async.wait_group 0;" ::: "memory")

#define LDSM_X4(r, a) \
    asm volatile("ldmatrix.sync.aligned.m8n8.x4.shared.b16 {%0,%1,%2,%3}, [%4];" \
        : "=r"((r)[0]), "=r"((r)[1]), "=r"((r)[2]), "=r"((r)[3]) : "r"(a))

#define MMA16816(d, a, b0, b1) \
    asm volatile("mma.sync.aligned.m16n8k16.row.col.f32.bf16.bf16.f32 " \
        "{%0,%1,%2,%3}, {%4,%5,%6,%7}, {%8,%9}, {%0,%1,%2,%3};" \
        : "+f"((d)[0]), "+f"((d)[1]), "+f"((d)[2]), "+f"((d)[3]) \
        : "r"((a)[0]), "r"((a)[1]), "r"((a)[2]), "r"((a)[3]), "r"(b0), "r"(b1))

// exp(s0), exp(s1) via one packed f16x2 EX2; inputs pre-multiplied by log2e
__device__ __forceinline__ void exp2pairf(float u0, float u1, float& e0, float& e1) {
    uint32_t h, e;
    asm("cvt.rn.f16x2.f32 %0, %1, %2;" : "=r"(h) : "f"(u1), "f"(u0)); // hi=u1, lo=u0
    asm("ex2.approx.f16x2 %0, %1;" : "=r"(e) : "r"(h));
    __half2 hv = *reinterpret_cast<__half2*>(&e);
    e0 = __low2float(hv);
    e1 = __high2float(hv);
}

// ---------------------------------------------------------------------------
// Kernel 1: row-normalize [zi; zj], fold in 1/sqrt(tau), emit bf16.
// One warp per row pair (r, r+BSZ).
// ---------------------------------------------------------------------------
__global__ __launch_bounds__(256) void normalize_kernel(
    const float* __restrict__ zi, const float* __restrict__ zj)
{
    int row = blockIdx.x * 8 + (threadIdx.x >> 5);   // 0..BSZ-1
    int l = threadIdx.x & 31;
    const float4* pa = (const float4*)(zi + (size_t)row * DDIM);
    const float4* pb = (const float4*)(zj + (size_t)row * DDIM);
    float4 a0 = pa[l], a1 = pa[l + 32];
    float4 b0 = pb[l], b1 = pb[l + 32];
    float sa = a0.x * a0.x + a0.y * a0.y + a0.z * a0.z + a0.w * a0.w
             + a1.x * a1.x + a1.y * a1.y + a1.z * a1.z + a1.w * a1.w;
    float sb = b0.x * b0.x + b0.y * b0.y + b0.z * b0.z + b0.w * b0.w
             + b1.x * b1.x + b1.y * b1.y + b1.z * b1.z + b1.w * b1.w;
    #pragma unroll
    for (int o = 16; o; o >>= 1) {
        sa += __shfl_xor_sync(0xffffffffu, sa, o);
        sb += __shfl_xor_sync(0xffffffffu, sb, o);
    }
    float ka = INV_SQRT_TAU / fmaxf(sqrtf(sa), COS_EPSF);
    float kb = INV_SQRT_TAU / fmaxf(sqrtf(sb), COS_EPSF);
    __nv_bfloat162* da = (__nv_bfloat162*)(g_zn + (size_t)row * DDIM);
    __nv_bfloat162* db = (__nv_bfloat162*)(g_zn + (size_t)(row + BSZ) * DDIM);
    da[2 * l + 0]  = __nv_bfloat162(__float2bfloat16(a0.x * ka), __float2bfloat16(a0.y * ka));
    da[2 * l + 1]  = __nv_bfloat162(__float2bfloat16(a0.z * ka), __float2bfloat16(a0.w * ka));
    da[64 + 2 * l] = __nv_bfloat162(__float2bfloat16(a1.x * ka), __float2bfloat16(a1.y * ka));
    da[65 + 2 * l] = __nv_bfloat162(__float2bfloat16(a1.z * ka), __float2bfloat16(a1.w * ka));
    db[2 * l + 0]  = __nv_bfloat162(__float2bfloat16(b0.x * kb), __float2bfloat16(b0.y * kb));
    db[2 * l + 1]  = __nv_bfloat162(__float2bfloat16(b0.z * kb), __float2bfloat16(b0.w * kb));
    db[64 + 2 * l] = __nv_bfloat162(__float2bfloat16(b1.x * kb), __float2bfloat16(b1.y * kb));
    db[65 + 2 * l] = __nv_bfloat162(__float2bfloat16(b1.z * kb), __float2bfloat16(b1.w * kb));
    if (l == 0) { g_negsum[row] = 0.0f; g_negsum[row + BSZ] = 0.0f; }
}

// ---------------------------------------------------------------------------
// Tile-class-specialized epilogue for 64x64 warp tiles; exp via packed
// f16x2 EX2. MODE 0: pure off-diag, MODE 1: pair tile (pos capture, exact
// f32 s), MODE 2: diagonal (diag exclusion, no col sums).
// ---------------------------------------------------------------------------
template <int MODE>
__device__ __forceinline__ void epilogue(
    float acc[4][8][4], int i0, int j0, int r0, int n0, int l)
{
    int gid = l >> 2, t4 = l & 3;
    float cs0[8], cs1[8];
    if (MODE != 2) {
        #pragma unroll
        for (int nt = 0; nt < 8; nt++) { cs0[nt] = 0.0f; cs1[nt] = 0.0f; }
    }

    #pragma unroll
    for (int mt = 0; mt < 4; mt++) {
        int ra = i0 + r0 + mt * 16 + gid;
        int rb = ra + 8;
        float rsa = 0.0f, rsb = 0.0f;
        #pragma unroll
        for (int nt = 0; nt < 8; nt++) {
            int col = j0 + n0 + nt * 8 + 2 * t4;
            float s0 = acc[mt][nt][0], s1 = acc[mt][nt][1];
            float s2 = acc[mt][nt][2], s3 = acc[mt][nt][3];
            float e0, e1, e2, e3;
            exp2pairf(s0 * LOG2E, s1 * LOG2E, e0, e1);
            exp2pairf(s2 * LOG2E, s3 * LOG2E, e2, e3);
            if (MODE == 1) {
                // pair tile: pair(ra) = ra + BSZ lands in this tile's columns
                if (col == ra + BSZ)     { g_spos[ra] = s0; g_spos[col] = s0; }
                if (col + 1 == ra + BSZ) { g_spos[ra] = s1; g_spos[col + 1] = s1; }
                if (col == rb + BSZ)     { g_spos[rb] = s2; g_spos[col] = s2; }
                if (col + 1 == rb + BSZ) { g_spos[rb] = s3; g_spos[col + 1] = s3; }
            }
            if (MODE == 2) {
                if (col == ra)     e0 = 0.0f;
                if (col + 1 == ra) e1 = 0.0f;
                if (col == rb)     e2 = 0.0f;
                if (col + 1 == rb) e3 = 0.0f;
            }
            rsa += e0 + e1; rsb += e2 + e3;
            if (MODE != 2) { cs0[nt] += e0 + e2; cs1[nt] += e1 + e3; }
        }
        rsa += __shfl_xor_sync(0xffffffffu, rsa, 1);
        rsa += __shfl_xor_sync(0xffffffffu, rsa, 2);
        rsb += __shfl_xor_sync(0xffffffffu, rsb, 1);
        rsb += __shfl_xor_sync(0xffffffffu, rsb, 2);
        if (t4 == 0) {
            atomicAdd(&g_negsum[ra], rsa);
            atomicAdd(&g_negsum[rb], rsb);
        }
    }

    if (MODE != 2) {
        // transpose contribution: column sums -> rows of the j-block
        #pragma unroll
        for (int nt = 0; nt < 8; nt++) {
            float c0 = cs0[nt], c1 = cs1[nt];
            c0 += __shfl_xor_sync(0xffffffffu, c0, 4);
            c0 += __shfl_xor_sync(0xffffffffu, c0, 8);
            c0 += __shfl_xor_sync(0xffffffffu, c0, 16);
            c1 += __shfl_xor_sync(0xffffffffu, c1, 4);
            c1 += __shfl_xor_sync(0xffffffffu, c1, 8);
            c1 += __shfl_xor_sync(0xffffffffu, c1, 16);
            if (gid == 0) {
                int col = j0 + n0 + nt * 8 + 2 * t4;
                atomicAdd(&g_negsum[col], c0);
                atomicAdd(&g_negsum[col + 1], c1);
            }
        }
    }
}

// ---------------------------------------------------------------------------
// Kernel 2: HMMA 128x128 tile of sim = zn @ zn^T, upper-triangle only,
// cp.async double-buffered over 4 k-stages of BK=64, ONE sync per stage.
// 4 warps (128 threads) in 2x2, 64x64 per warp. Occupancy 3 CTAs/SM:
// register pressure cut via address-algebra collapse (stage-load offsets
// are one base + it*2048) and bf-first fragment ordering (20 frag regs).
// ---------------------------------------------------------------------------
__global__ __launch_bounds__(128, 3) void sim_kernel()
{
    int bi = blockIdx.y, bj = blockIdx.x;
    if (bj < bi) return;                      // symmetry: upper triangle only
    extern __shared__ char smem[];
    int i0 = bi * TILE, j0 = bj * TILE;
    int tid = threadIdx.x, wid = tid >> 5, l = tid & 31;
    int r0 = (wid >> 1) * 64;                 // warp row offset (2x2 warps)
    int n0 = (wid & 1) * 64;                  // warp col offset
    uint32_t sbase = smem_u32(smem);

    float acc[4][8][4] = {};

    // ldmatrix lane addressing
    int a_row = l & 15, a_hi = l >> 4;
    int b_row = (l & 7) + ((l >> 4) << 3), b_hi = (l >> 3) & 1;

    // Stage-load address algebra: lane covers (base_r + 16*it, c=tid&7);
    // 16*it preserves r&7, so the swizzle XOR is it-invariant:
    //   smem off = base_soff + it*2048
    //   gmem off = base ptr + it*2048 bytes (16 rows * 128B along BK=64 panel)
    int base_r = tid >> 3;
    int c      = tid & 7;
    uint32_t base_soff = (uint32_t)(base_r * 128 + ((c ^ (base_r & 7)) << 4));
    const char* gA = (const char*)g_zn + ((size_t)(i0 + base_r) * 256 + c * 16) * 2 / 2;
    const char* gB = (const char*)g_zn + ((size_t)(j0 + base_r) * 256 + c * 16) * 2 / 2;
    // rows are 512 B (256 bf16); step of 16 rows = 8192 B
    gA = (const char*)g_zn + (size_t)(i0 + base_r) * 512 + c * 16;
    gB = (const char*)g_zn + (size_t)(j0 + base_r) * 512 + c * 16;

    // prologue: stage 0 (k-bytes 0..127 of each row) into buffer 0
    #pragma unroll
    for (int it = 0; it < 8; it++) {
        cp16(sbase + base_soff + it * 2048,               gA + (size_t)it * 8192);
        cp16(sbase + STAGE_BYTES + base_soff + it * 2048, gB + (size_t)it * 8192);
    }
    CP_COMMIT();

    #pragma unroll
    for (int kc = 0; kc < 4; kc++) {
        int s = kc & 1;
        CP_WAIT0();
        __syncthreads();                      // data visible; prior stage reads done
        if (kc < 3) {                         // prefetch next stage (k offset 128B/stage)
            uint32_t nb = sbase + (uint32_t)((s ^ 1) * 2 * STAGE_BYTES);
            size_t ko = (size_t)(kc + 1) * 128;
            #pragma unroll
            for (int it = 0; it < 8; it++) {
                cp16(nb + base_soff + it * 2048,               gA + ko + (size_t)it * 8192);
                cp16(nb + STAGE_BYTES + base_soff + it * 2048, gB + ko + (size_t)it * 8192);
            }
            CP_COMMIT();
        }
        uint32_t sA = sbase + (uint32_t)(s * 2 * STAGE_BYTES);
        uint32_t sB = sA + STAGE_BYTES;

        #pragma unroll
        for (int ks = 0; ks < 4; ks++) {
            uint32_t bf[4][4];
            #pragma unroll
            for (int np = 0; np < 4; np++) {
                int row = n0 + np * 16 + b_row;
                LDSM_X4(bf[np], sB + row * 128 + (((2 * ks + b_hi) ^ (row & 7)) << 4));
            }
            #pragma unroll
            for (int mt = 0; mt < 4; mt++) {
                uint32_t af[4];
                int row = r0 + mt * 16 + a_row;
                LDSM_X4(af, sA + row * 128 + (((2 * ks + a_hi) ^ (row & 7)) << 4));
                #pragma unroll
                for (int np = 0; np < 4; np++) {
                    MMA16816(acc[mt][2 * np + 0], af, bf[np][0], bf[np][1]);
                    MMA16816(acc[mt][2 * np + 1], af, bf[np][2], bf[np][3]);
                }
            }
        }
    }

    // ---- specialized epilogue ----
    int d = bj - bi;
    if (d == 0)          epilogue<2>(acc, i0, j0, r0, n0, l);
    else if (d == PAIRD) epilogue<1>(acc, i0, j0, r0, n0, l);
    else                 epilogue<0>(acc, i0, j0, r0, n0, l);
}

// ---------------------------------------------------------------------------
// Kernel 3: loss = mean( log(negsum + eps) - s_pos )
// ---------------------------------------------------------------------------
__global__ __launch_bounds__(1024) void loss_kernel(float* __restrict__ out)
{
    __shared__ float sh[32];
    int t = threadIdx.x, l = t & 31, w = t >> 5;
    float acc = 0.0f;
    #pragma unroll
    for (int it = 0; it < 8; it++) {
        int i = t + it * 1024;
        acc += __logf(g_negsum[i] + EPSF) - g_spos[i];
    }
    #pragma unroll
    for (int o = 16; o; o >>= 1) acc += __shfl_xor_sync(0xffffffffu, acc, o);
    if (l == 0) sh[w] = acc;
    __syncthreads();
    if (w == 0) {
        acc = sh[l];
        #pragma unroll
        for (int o = 16; o; o >>= 1) acc += __shfl_xor_sync(0xffffffffu, acc, o);
        if (l == 0) out[0] = acc / (float)NROWS;
    }
}

// ---------------------------------------------------------------------------
extern "C" void kernel_launch(void* const* d_in, const int* in_sizes, int n_in,
                              void* d_out, int out_size)
{
    const float* zi = (const float*)d_in[0];
    const float* zj = (const float*)d_in[1];
    float* out = (float*)d_out;

    static int inited = 0;
    if (!inited) {
        cudaFuncSetAttribute(sim_kernel,
                             cudaFuncAttributeMaxDynamicSharedMemorySize,
                             SMEM_BYTES);
        inited = 1;
    }

    normalize_kernel<<<BSZ / 8, 256>>>(zi, zj);
    dim3 grid(NROWS / TILE, NROWS / TILE);    // 64 x 64, lower triangle exits
    sim_kernel<<<grid, 128, SMEM_BYTES>>>();
    loss_kernel<<<1, 1024>>>(out);
}

// round 14
// speedup vs baseline: 1.2870x; 1.2870x over previous
#include <cuda_runtime.h>
#include <cuda_bf16.h>
#include <cstdint>
#include <math.h>

#define BSZ   4096
#define NROWS 8192
#define DDIM  256
#define EPSF      1e-8f
#define COS_EPSF  1e-8f
#define INV_SQRT_TAU 1.4142135623730951f   // 1/sqrt(0.5)
#define LOG2E 1.4426950408889634f

#define TILE 128
#define NBLK 64                            // 8192 / 128 row-blocks
#define NTILES 2080                        // NBLK*(NBLK+1)/2 upper-tri tiles
#define PAIRD 32                           // BSZ / TILE: block distance of pos pairs
#define STAGE_BYTES (TILE * 128)           // 16 KB per operand per stage (BK=64 bf16)
#define SMEM_BYTES (4 * STAGE_BYTES)       // A0,B0,A1,B1 = 64 KB
#define STAGGER_CYC 3000                   // ~half tile period: de-phase slot B

// Scratch (device globals; no allocation allowed)
__device__ __nv_bfloat16 g_zn[NROWS * DDIM];   // normalized * 1/sqrt(tau)
__device__ float g_negsum[NROWS];
__device__ float g_spos[NROWS];

__device__ __forceinline__ uint32_t smem_u32(const void* p) {
    uint32_t a;
    asm("{ .reg .u64 t; cvta.to.shared.u64 t, %1; cvt.u32.u64 %0, t; }"
        : "=r"(a) : "l"(p));
    return a;
}
__device__ __forceinline__ void cp16(uint32_t dst, const void* src) {
    asm volatile("cp.async.cg.shared.global [%0], [%1], 16;"
                 :: "r"(dst), "l"(src) : "memory");
}
#define CP_COMMIT() asm volatile("cp.async.commit_group;" ::: "memory")
#define CP_WAIT0()  asm volatile("cp.async.wait_group 0;" ::: "memory")

#define LDSM_X4(r, a) \
    asm volatile("ldmatrix.sync.aligned.m8n8.x4.shared.b16 {%0,%1,%2,%3}, [%4];" \
        : "=r"((r)[0]), "=r"((r)[1]), "=r"((r)[2]), "=r"((r)[3]) : "r"(a))

#define MMA16816(d, a, b0, b1) \
    asm volatile("mma.sync.aligned.m16n8k16.row.col.f32.bf16.bf16.f32 " \
        "{%0,%1,%2,%3}, {%4,%5,%6,%7}, {%8,%9}, {%0,%1,%2,%3};" \
        : "+f"((d)[0]), "+f"((d)[1]), "+f"((d)[2]), "+f"((d)[3]) \
        : "r"((a)[0]), "r"((a)[1]), "r"((a)[2]), "r"((a)[3]), "r"(b0), "r"(b1))

// exp(s0), exp(s1) via one packed f16x2 EX2; inputs pre-multiplied by log2e
__device__ __forceinline__ void exp2pairf(float u0, float u1, float& e0, float& e1) {
    uint32_t h, e;
    asm("cvt.rn.f16x2.f32 %0, %1, %2;" : "=r"(h) : "f"(u1), "f"(u0)); // hi=u1, lo=u0
    asm("ex2.approx.f16x2 %0, %1;" : "=r"(e) : "r"(h));
    __half2 hv = *reinterpret_cast<__half2*>(&e);
    e0 = __low2float(hv);
    e1 = __high2float(hv);
}

// linear upper-triangle index -> (bi, bj), bi <= bj
__device__ __forceinline__ void tile_coords(int t, int& bi, int& bj) {
    int b = (int)((2.0f * NBLK + 1.0f
                   - sqrtf((2.0f * NBLK + 1.0f) * (2.0f * NBLK + 1.0f) - 8.0f * t)) * 0.5f);
    while ((b + 1) * (2 * NBLK + 1 - (b + 1)) / 2 <= t) b++;
    while (b * (2 * NBLK + 1 - b) / 2 > t) b--;
    bi = b;
    bj = b + (t - b * (2 * NBLK + 1 - b) / 2);
}

// ---------------------------------------------------------------------------
// Kernel 1: row-normalize [zi; zj], fold in 1/sqrt(tau), emit bf16.
// One warp per row pair (r, r+BSZ).
// ---------------------------------------------------------------------------
__global__ __launch_bounds__(256) void normalize_kernel(
    const float* __restrict__ zi, const float* __restrict__ zj)
{
    int row = blockIdx.x * 8 + (threadIdx.x >> 5);   // 0..BSZ-1
    int l = threadIdx.x & 31;
    const float4* pa = (const float4*)(zi + (size_t)row * DDIM);
    const float4* pb = (const float4*)(zj + (size_t)row * DDIM);
    float4 a0 = pa[l], a1 = pa[l + 32];
    float4 b0 = pb[l], b1 = pb[l + 32];
    float sa = a0.x * a0.x + a0.y * a0.y + a0.z * a0.z + a0.w * a0.w
             + a1.x * a1.x + a1.y * a1.y + a1.z * a1.z + a1.w * a1.w;
    float sb = b0.x * b0.x + b0.y * b0.y + b0.z * b0.z + b0.w * b0.w
             + b1.x * b1.x + b1.y * b1.y + b1.z * b1.z + b1.w * b1.w;
    #pragma unroll
    for (int o = 16; o; o >>= 1) {
        sa += __shfl_xor_sync(0xffffffffu, sa, o);
        sb += __shfl_xor_sync(0xffffffffu, sb, o);
    }
    float ka = INV_SQRT_TAU / fmaxf(sqrtf(sa), COS_EPSF);
    float kb = INV_SQRT_TAU / fmaxf(sqrtf(sb), COS_EPSF);
    __nv_bfloat162* da = (__nv_bfloat162*)(g_zn + (size_t)row * DDIM);
    __nv_bfloat162* db = (__nv_bfloat162*)(g_zn + (size_t)(row + BSZ) * DDIM);
    da[2 * l + 0]  = __nv_bfloat162(__float2bfloat16(a0.x * ka), __float2bfloat16(a0.y * ka));
    da[2 * l + 1]  = __nv_bfloat162(__float2bfloat16(a0.z * ka), __float2bfloat16(a0.w * ka));
    da[64 + 2 * l] = __nv_bfloat162(__float2bfloat16(a1.x * ka), __float2bfloat16(a1.y * ka));
    da[65 + 2 * l] = __nv_bfloat162(__float2bfloat16(a1.z * ka), __float2bfloat16(a1.w * ka));
    db[2 * l + 0]  = __nv_bfloat162(__float2bfloat16(b0.x * kb), __float2bfloat16(b0.y * kb));
    db[2 * l + 1]  = __nv_bfloat162(__float2bfloat16(b0.z * kb), __float2bfloat16(b0.w * kb));
    db[64 + 2 * l] = __nv_bfloat162(__float2bfloat16(b1.x * kb), __float2bfloat16(b1.y * kb));
    db[65 + 2 * l] = __nv_bfloat162(__float2bfloat16(b1.z * kb), __float2bfloat16(b1.w * kb));
    if (l == 0) { g_negsum[row] = 0.0f; g_negsum[row + BSZ] = 0.0f; }
}

// ---------------------------------------------------------------------------
// Tile-class-specialized epilogue for 64x64 warp tiles; exp via packed
// f16x2 EX2. MODE 0: pure off-diag, MODE 1: pair tile (pos capture, exact
// f32 s), MODE 2: diagonal (diag exclusion, no col sums).
// ---------------------------------------------------------------------------
template <int MODE>
__device__ __forceinline__ void epilogue(
    float acc[4][8][4], int i0, int j0, int r0, int n0, int l)
{
    int gid = l >> 2, t4 = l & 3;
    float cs0[8], cs1[8];
    if (MODE != 2) {
        #pragma unroll
        for (int nt = 0; nt < 8; nt++) { cs0[nt] = 0.0f; cs1[nt] = 0.0f; }
    }

    #pragma unroll
    for (int mt = 0; mt < 4; mt++) {
        int ra = i0 + r0 + mt * 16 + gid;
        int rb = ra + 8;
        float rsa = 0.0f, rsb = 0.0f;
        #pragma unroll
        for (int nt = 0; nt < 8; nt++) {
            int col = j0 + n0 + nt * 8 + 2 * t4;
            float s0 = acc[mt][nt][0], s1 = acc[mt][nt][1];
            float s2 = acc[mt][nt][2], s3 = acc[mt][nt][3];
            float e0, e1, e2, e3;
            exp2pairf(s0 * LOG2E, s1 * LOG2E, e0, e1);
            exp2pairf(s2 * LOG2E, s3 * LOG2E, e2, e3);
            if (MODE == 1) {
                // pair tile: pair(ra) = ra + BSZ lands in this tile's columns
                if (col == ra + BSZ)     { g_spos[ra] = s0; g_spos[col] = s0; }
                if (col + 1 == ra + BSZ) { g_spos[ra] = s1; g_spos[col + 1] = s1; }
                if (col == rb + BSZ)     { g_spos[rb] = s2; g_spos[col] = s2; }
                if (col + 1 == rb + BSZ) { g_spos[rb] = s3; g_spos[col + 1] = s3; }
            }
            if (MODE == 2) {
                if (col == ra)     e0 = 0.0f;
                if (col + 1 == ra) e1 = 0.0f;
                if (col == rb)     e2 = 0.0f;
                if (col + 1 == rb) e3 = 0.0f;
            }
            rsa += e0 + e1; rsb += e2 + e3;
            if (MODE != 2) { cs0[nt] += e0 + e2; cs1[nt] += e1 + e3; }
        }
        rsa += __shfl_xor_sync(0xffffffffu, rsa, 1);
        rsa += __shfl_xor_sync(0xffffffffu, rsa, 2);
        rsb += __shfl_xor_sync(0xffffffffu, rsb, 1);
        rsb += __shfl_xor_sync(0xffffffffu, rsb, 2);
        if (t4 == 0) {
            atomicAdd(&g_negsum[ra], rsa);
            atomicAdd(&g_negsum[rb], rsb);
        }
    }

    if (MODE != 2) {
        // transpose contribution: column sums -> rows of the j-block
        #pragma unroll
        for (int nt = 0; nt < 8; nt++) {
            float c0 = cs0[nt], c1 = cs1[nt];
            c0 += __shfl_xor_sync(0xffffffffu, c0, 4);
            c0 += __shfl_xor_sync(0xffffffffu, c0, 8);
            c0 += __shfl_xor_sync(0xffffffffu, c0, 16);
            c1 += __shfl_xor_sync(0xffffffffu, c1, 4);
            c1 += __shfl_xor_sync(0xffffffffu, c1, 8);
            c1 += __shfl_xor_sync(0xffffffffu, c1, 16);
            if (gid == 0) {
                int col = j0 + n0 + nt * 8 + 2 * t4;
                atomicAdd(&g_negsum[col], c0);
                atomicAdd(&g_negsum[col + 1], c1);
            }
        }
    }
}

// ---------------------------------------------------------------------------
// Kernel 2: HMMA 128x128 tile of sim = zn @ zn^T, 1D triangular grid,
// cp.async double-buffered over 4 k-stages of BK=64, ONE sync per stage.
// 4 warps (128 threads) in 2x2, 64x64 per warp, 2 CTAs/SM.
// Wave-1 slot-B CTAs (blockIdx 148..295) spin ~STAGGER_CYC to anti-phase
// the two co-resident CTAs (epilogue hides under the other CTA's MMA).
// Stage layout: row r (0..127) * 128B, chunk c (0..7): off=r*128+((c^(r&7))<<4)
// ---------------------------------------------------------------------------
__global__ __launch_bounds__(128, 2) void sim_kernel()
{
    int bi, bj;
    tile_coords((int)blockIdx.x, bi, bj);

    // one-time phase stagger for the second co-resident CTA of each SM
    if (blockIdx.x >= 148 && blockIdx.x < 296) {
        long long t0 = clock64();
        while (clock64() - t0 < STAGGER_CYC) { }
    }

    extern __shared__ char smem[];
    int i0 = bi * TILE, j0 = bj * TILE;
    int tid = threadIdx.x, wid = tid >> 5, l = tid & 31;
    int r0 = (wid >> 1) * 64;                 // warp row offset (2x2 warps)
    int n0 = (wid & 1) * 64;                  // warp col offset
    uint32_t sbase = smem_u32(smem);

    float acc[4][8][4] = {};

    // ldmatrix lane addressing
    int a_row = l & 15, a_hi = l >> 4;
    int b_row = (l & 7) + ((l >> 4) << 3), b_hi = (l >> 3) & 1;

    const uint4* gz = (const uint4*)g_zn;     // 32 uint4 per 256-elem row

    // per-thread load coords (8 x 16B per operand per stage, 128 threads)
    uint32_t loff[8]; int lr[8], lc[8];
    #pragma unroll
    for (int it = 0; it < 8; it++) {
        int f = tid + it * 128;               // 0..1023
        lr[it] = f >> 3; lc[it] = f & 7;
        loff[it] = (uint32_t)(lr[it] * 128 + ((lc[it] ^ (lr[it] & 7)) << 4));
    }

    // prologue: stage 0 into buffer 0
    #pragma unroll
    for (int it = 0; it < 8; it++) {
        cp16(sbase + loff[it],               &gz[(size_t)(i0 + lr[it]) * 32 + lc[it]]);
        cp16(sbase + STAGE_BYTES + loff[it], &gz[(size_t)(j0 + lr[it]) * 32 + lc[it]]);
    }
    CP_COMMIT();

    #pragma unroll
    for (int kc = 0; kc < 4; kc++) {
        int s = kc & 1;
        CP_WAIT0();
        __syncthreads();                      // data visible; prior stage's reads done
        if (kc < 3) {                         // prefetch next stage into other buffer
            uint32_t nb = sbase + (uint32_t)((s ^ 1) * 2 * STAGE_BYTES);
            #pragma unroll
            for (int it = 0; it < 8; it++) {
                cp16(nb + loff[it],               &gz[(size_t)(i0 + lr[it]) * 32 + (kc + 1) * 8 + lc[it]]);
                cp16(nb + STAGE_BYTES + loff[it], &gz[(size_t)(j0 + lr[it]) * 32 + (kc + 1) * 8 + lc[it]]);
            }
            CP_COMMIT();
        }
        uint32_t sA = sbase + (uint32_t)(s * 2 * STAGE_BYTES);
        uint32_t sB = sA + STAGE_BYTES;

        #pragma unroll
        for (int ks = 0; ks < 4; ks++) {
            uint32_t af[4][4], bf[4][4];
            #pragma unroll
            for (int mt = 0; mt < 4; mt++) {
                int row = r0 + mt * 16 + a_row;
                LDSM_X4(af[mt], sA + row * 128 + (((2 * ks + a_hi) ^ (row & 7)) << 4));
            }
            #pragma unroll
            for (int np = 0; np < 4; np++) {
                int row = n0 + np * 16 + b_row;
                LDSM_X4(bf[np], sB + row * 128 + (((2 * ks + b_hi) ^ (row & 7)) << 4));
            }
            #pragma unroll
            for (int mt = 0; mt < 4; mt++)
                #pragma unroll
                for (int np = 0; np < 4; np++) {
                    MMA16816(acc[mt][2 * np + 0], af[mt], bf[np][0], bf[np][1]);
                    MMA16816(acc[mt][2 * np + 1], af[mt], bf[np][2], bf[np][3]);
                }
        }
    }

    // ---- specialized epilogue ----
    int d = bj - bi;
    if (d == 0)          epilogue<2>(acc, i0, j0, r0, n0, l);
    else if (d == PAIRD) epilogue<1>(acc, i0, j0, r0, n0, l);
    else                 epilogue<0>(acc, i0, j0, r0, n0, l);
}

// ---------------------------------------------------------------------------
// Kernel 3: loss = mean( log(negsum + eps) - s_pos )
// ---------------------------------------------------------------------------
__global__ __launch_bounds__(1024) void loss_kernel(float* __restrict__ out)
{
    __shared__ float sh[32];
    int t = threadIdx.x, l = t & 31, w = t >> 5;
    float acc = 0.0f;
    #pragma unroll
    for (int it = 0; it < 8; it++) {
        int i = t + it * 1024;
        acc += __logf(g_negsum[i] + EPSF) - g_spos[i];
    }
    #pragma unroll
    for (int o = 16; o; o >>= 1) acc += __shfl_xor_sync(0xffffffffu, acc, o);
    if (l == 0) sh[w] = acc;
    __syncthreads();
    if (w == 0) {
        acc = sh[l];
        #pragma unroll
        for (int o = 16; o; o >>= 1) acc += __shfl_xor_sync(0xffffffffu, acc, o);
        if (l == 0) out[0] = acc / (float)NROWS;
    }
}

// ---------------------------------------------------------------------------
extern "C" void kernel_launch(void* const* d_in, const int* in_sizes, int n_in,
                              void* d_out, int out_size)
{
    const float* zi = (const float*)d_in[0];
    const float* zj = (const float*)d_in[1];
    float* out = (float*)d_out;

    static int inited = 0;
    if (!inited) {
        cudaFuncSetAttribute(sim_kernel,
                             cudaFuncAttributeMaxDynamicSharedMemorySize,
                             SMEM_BYTES);
        inited = 1;
    }

    normalize_kernel<<<BSZ / 8, 256>>>(zi, zj);
    sim_kernel<<<NTILES, 128, SMEM_BYTES>>>();
    loss_kernel<<<1, 1024>>>(out);
}